// round 1
// baseline (speedup 1.0000x reference)
#include <cuda_runtime.h>
#include <math.h>

// Problem constants
#define BB 2
#define TT 128
#define DD 1024
#define HH 8
#define RRm 8
#define DK 64
#define DV 64
#define NPROJ 2176           // 512 q | 512 k | 512 v | 64 beta | 64 tg | 512 g
#define NROWS 256            // B*T

// Scratch (no allocations allowed)
__device__ __align__(16) float g_proj[NROWS * NPROJ];     // 2.2 MB
__device__ __align__(16) float g_y[NROWS * HH * DV];      // 512 KB

__device__ __forceinline__ float sigmoidf_(float x) { return 1.f / (1.f + expf(-x)); }

// ---------------------------------------------------------------------------
// Zero the y accumulator
// ---------------------------------------------------------------------------
__global__ void zero_y_kernel() {
  int i = blockIdx.x * blockDim.x + threadIdx.x;
  if (i < NROWS * HH * DV) g_y[i] = 0.f;
}

// ---------------------------------------------------------------------------
// Fused projection GEMM: proj[256, 2176] = x @ [Wq|Wk|Wv|Wb|Wtg|Wg]
// 64x64 tiles, 256 threads, 4x4 microtile. Sigmoid applied for cols >= 1536.
// ---------------------------------------------------------------------------
__global__ __launch_bounds__(256) void proj_gemm_kernel(
    const float* __restrict__ x,
    const float* __restrict__ Wq, const float* __restrict__ Wk,
    const float* __restrict__ Wv, const float* __restrict__ Wb,
    const float* __restrict__ Wtg, const float* __restrict__ Wg) {
  __shared__ float As[16][64];
  __shared__ float Bs[16][64];

  const int colBase = blockIdx.x * 64;
  const int rowBase = blockIdx.y * 64;

  const float* W; int lc, ldw;
  if (colBase < 512)       { W = Wq;  lc = colBase;        ldw = 512; }
  else if (colBase < 1024) { W = Wk;  lc = colBase - 512;  ldw = 512; }
  else if (colBase < 1536) { W = Wv;  lc = colBase - 1024; ldw = 512; }
  else if (colBase < 1600) { W = Wb;  lc = colBase - 1536; ldw = 64;  }
  else if (colBase < 1664) { W = Wtg; lc = colBase - 1600; ldw = 64;  }
  else                     { W = Wg;  lc = colBase - 1664; ldw = 512; }

  const int tid = threadIdx.x;
  const int ty = tid >> 4, tx = tid & 15;       // compute mapping
  const int lr = tid >> 2, kg = tid & 3;        // A load mapping
  const int lk = tid >> 4, c4 = (tid & 15) << 2;// B load mapping

  float acc[4][4];
#pragma unroll
  for (int i = 0; i < 4; i++)
#pragma unroll
    for (int j = 0; j < 4; j++) acc[i][j] = 0.f;

  for (int kb = 0; kb < DD; kb += 16) {
    float4 av = *(const float4*)(x + (rowBase + lr) * DD + kb + kg * 4);
    float4 bv = *(const float4*)(W + (kb + lk) * ldw + lc + c4);
    __syncthreads();
    As[kg * 4 + 0][lr] = av.x;
    As[kg * 4 + 1][lr] = av.y;
    As[kg * 4 + 2][lr] = av.z;
    As[kg * 4 + 3][lr] = av.w;
    *(float4*)(&Bs[lk][c4]) = bv;
    __syncthreads();
#pragma unroll
    for (int kk = 0; kk < 16; kk++) {
      float a0 = As[kk][ty * 4 + 0];
      float a1 = As[kk][ty * 4 + 1];
      float a2 = As[kk][ty * 4 + 2];
      float a3 = As[kk][ty * 4 + 3];
      float4 bbv = *(float4*)(&Bs[kk][tx * 4]);
      acc[0][0] = fmaf(a0, bbv.x, acc[0][0]);
      acc[0][1] = fmaf(a0, bbv.y, acc[0][1]);
      acc[0][2] = fmaf(a0, bbv.z, acc[0][2]);
      acc[0][3] = fmaf(a0, bbv.w, acc[0][3]);
      acc[1][0] = fmaf(a1, bbv.x, acc[1][0]);
      acc[1][1] = fmaf(a1, bbv.y, acc[1][1]);
      acc[1][2] = fmaf(a1, bbv.z, acc[1][2]);
      acc[1][3] = fmaf(a1, bbv.w, acc[1][3]);
      acc[2][0] = fmaf(a2, bbv.x, acc[2][0]);
      acc[2][1] = fmaf(a2, bbv.y, acc[2][1]);
      acc[2][2] = fmaf(a2, bbv.z, acc[2][2]);
      acc[2][3] = fmaf(a2, bbv.w, acc[2][3]);
      acc[3][0] = fmaf(a3, bbv.x, acc[3][0]);
      acc[3][1] = fmaf(a3, bbv.y, acc[3][1]);
      acc[3][2] = fmaf(a3, bbv.z, acc[3][2]);
      acc[3][3] = fmaf(a3, bbv.w, acc[3][3]);
    }
  }

  const bool sig = (colBase >= 1536);
#pragma unroll
  for (int i = 0; i < 4; i++) {
#pragma unroll
    for (int j = 0; j < 4; j++) {
      float vv = acc[i][j];
      if (sig) vv = sigmoidf_(vv);
      g_proj[(rowBase + ty * 4 + i) * NPROJ + colBase + tx * 4 + j] = vv;
    }
  }
}

// ---------------------------------------------------------------------------
// Sequential scan. One CTA per (b,h,r) chain: 128 CTAs, 256 threads.
// Thread owns v = tid/4 (row), k-range [16*(tid%4), +16) of the 64x64 state.
// State (sr, si) register-resident: 16+16 floats per thread.
// ---------------------------------------------------------------------------
__global__ __launch_bounds__(256) void scan_kernel(
    const float* __restrict__ mode_logits,
    const float* __restrict__ log_decay,
    const float* __restrict__ omega_log_scale) {
  const int cid = blockIdx.x;        // 0..127
  const int b = cid >> 6;
  const int h = (cid >> 3) & 7;
  const int r = cid & 7;
  const int tid = threadIdx.x;
  const int v = tid >> 2;
  const int q4 = tid & 3;
  const int k0 = q4 * 16;

  // mode weight: softmax over R for this head
  float ml[RRm];
  float mx = -1e30f;
#pragma unroll
  for (int i = 0; i < RRm; i++) { ml[i] = mode_logits[h * RRm + i]; mx = fmaxf(mx, ml[i]); }
  float ssum = 0.f;
#pragma unroll
  for (int i = 0; i < RRm; i++) ssum += expf(ml[i] - mx);
  const float mw = expf(ml[r] - mx) / ssum;

  // rho = exp(-softplus(log_decay))
  const float ldv = log_decay[h * RRm + r];
  const float sp = (ldv > 20.f) ? ldv : log1pf(expf(ldv));
  const float rho = expf(-sp);
  const float osc = expf(omega_log_scale[h * RRm + r]);

  // per-k rotation: omega = osc * 10000^{-(k&~1)/64}
  float cw[16], sw[16], sr[16], si[16];
  const float c_ln = 9.210340371976184f / 64.f;  // ln(10000)/64
#pragma unroll
  for (int j = 0; j < 16; j++) {
    int k = k0 + j;
    float p = (float)(k & ~1);
    float om = osc * expf(-p * c_ln);
    sw[j] = sinf(om);
    cw[j] = cosf(om);
    sr[j] = 0.f;
    si[j] = 0.f;
  }

  const int qoff = h * DK + k0;
  float* yrow_base = g_y + (b * TT * HH + h) * DV + v;

  for (int t = 0; t < TT; t++) {
    const float* row = g_proj + (b * TT + t) * NPROJ;

    float kt[16], qt[16];
#pragma unroll
    for (int g4 = 0; g4 < 4; g4++) {
      float4 kv = *(const float4*)(row + 512 + qoff + g4 * 4);
      float4 qv = *(const float4*)(row + 0 + qoff + g4 * 4);
      kt[g4 * 4 + 0] = kv.x; kt[g4 * 4 + 1] = kv.y;
      kt[g4 * 4 + 2] = kv.z; kt[g4 * 4 + 3] = kv.w;
      qt[g4 * 4 + 0] = qv.x; qt[g4 * 4 + 1] = qv.y;
      qt[g4 * 4 + 2] = qv.z; qt[g4 * 4 + 3] = qv.w;
    }
    const float vtv  = row[1024 + h * DV + v];
    const float beta = row[1536 + h * RRm + r];  // pre-sigmoided
    const float tg   = row[1600 + h * RRm + r];  // pre-sigmoided
    const float decay = tg * rho;

    // rotate state (complex mult by decay * e^{i omega}) + pred partial
    float pred = 0.f;
#pragma unroll
    for (int j = 0; j < 16; j++) {
      float dc = decay * cw[j];
      float ds = decay * sw[j];
      float m1 = ds * si[j];
      float rr = fmaf(dc, sr[j], -m1);
      float m2 = dc * si[j];
      float ri = fmaf(ds, sr[j], m2);
      si[j] = ri;
      sr[j] = rr;                        // sr temporarily holds rot_r
      pred = fmaf(rr, kt[j], pred);
    }
    pred += __shfl_xor_sync(0xffffffffu, pred, 1);
    pred += __shfl_xor_sync(0xffffffffu, pred, 2);

    const float w = beta * (vtv - pred);

    float rd = 0.f;
#pragma unroll
    for (int j = 0; j < 16; j++) {
      sr[j] = fmaf(w, kt[j], sr[j]);     // sr_new = rot_r + beta*err*k
      rd = fmaf(sr[j], qt[j], rd);
    }
    rd += __shfl_xor_sync(0xffffffffu, rd, 1);
    rd += __shfl_xor_sync(0xffffffffu, rd, 2);

    if (q4 == 0) atomicAdd(yrow_base + t * (HH * DV), mw * rd);
  }
}

// ---------------------------------------------------------------------------
// Output GEMM: out[256,1024] = (y * gate)[256,512] @ Wo[512,1024]
// ---------------------------------------------------------------------------
__global__ __launch_bounds__(256) void out_gemm_kernel(
    const float* __restrict__ Wo, float* __restrict__ out) {
  __shared__ float As[16][64];
  __shared__ float Bs[16][64];

  const int colBase = blockIdx.x * 64;  // 0..1023
  const int rowBase = blockIdx.y * 64;  // 0..255

  const int tid = threadIdx.x;
  const int ty = tid >> 4, tx = tid & 15;
  const int lr = tid >> 2, kg = tid & 3;
  const int lk = tid >> 4, c4 = (tid & 15) << 2;

  float acc[4][4];
#pragma unroll
  for (int i = 0; i < 4; i++)
#pragma unroll
    for (int j = 0; j < 4; j++) acc[i][j] = 0.f;

  for (int kb = 0; kb < HH * DV; kb += 16) {
    float4 yv = *(const float4*)(g_y + (rowBase + lr) * (HH * DV) + kb + kg * 4);
    float4 gv = *(const float4*)(g_proj + (rowBase + lr) * NPROJ + 1664 + kb + kg * 4);
    float4 av;
    av.x = yv.x * gv.x; av.y = yv.y * gv.y;
    av.z = yv.z * gv.z; av.w = yv.w * gv.w;
    float4 bv = *(const float4*)(Wo + (kb + lk) * DD + colBase + c4);
    __syncthreads();
    As[kg * 4 + 0][lr] = av.x;
    As[kg * 4 + 1][lr] = av.y;
    As[kg * 4 + 2][lr] = av.z;
    As[kg * 4 + 3][lr] = av.w;
    *(float4*)(&Bs[lk][c4]) = bv;
    __syncthreads();
#pragma unroll
    for (int kk = 0; kk < 16; kk++) {
      float a0 = As[kk][ty * 4 + 0];
      float a1 = As[kk][ty * 4 + 1];
      float a2 = As[kk][ty * 4 + 2];
      float a3 = As[kk][ty * 4 + 3];
      float4 bbv = *(float4*)(&Bs[kk][tx * 4]);
      acc[0][0] = fmaf(a0, bbv.x, acc[0][0]);
      acc[0][1] = fmaf(a0, bbv.y, acc[0][1]);
      acc[0][2] = fmaf(a0, bbv.z, acc[0][2]);
      acc[0][3] = fmaf(a0, bbv.w, acc[0][3]);
      acc[1][0] = fmaf(a1, bbv.x, acc[1][0]);
      acc[1][1] = fmaf(a1, bbv.y, acc[1][1]);
      acc[1][2] = fmaf(a1, bbv.z, acc[1][2]);
      acc[1][3] = fmaf(a1, bbv.w, acc[1][3]);
      acc[2][0] = fmaf(a2, bbv.x, acc[2][0]);
      acc[2][1] = fmaf(a2, bbv.y, acc[2][1]);
      acc[2][2] = fmaf(a2, bbv.z, acc[2][2]);
      acc[2][3] = fmaf(a2, bbv.w, acc[2][3]);
      acc[3][0] = fmaf(a3, bbv.x, acc[3][0]);
      acc[3][1] = fmaf(a3, bbv.y, acc[3][1]);
      acc[3][2] = fmaf(a3, bbv.z, acc[3][2]);
      acc[3][3] = fmaf(a3, bbv.w, acc[3][3]);
    }
  }

#pragma unroll
  for (int i = 0; i < 4; i++)
#pragma unroll
    for (int j = 0; j < 4; j++)
      out[(rowBase + ty * 4 + i) * DD + colBase + tx * 4 + j] = acc[i][j];
}

// ---------------------------------------------------------------------------
// Entry point
// ---------------------------------------------------------------------------
extern "C" void kernel_launch(void* const* d_in, const int* in_sizes, int n_in,
                              void* d_out, int out_size) {
  const float* x    = (const float*)d_in[0];
  const float* Wq   = (const float*)d_in[1];
  const float* Wk   = (const float*)d_in[2];
  const float* Wv   = (const float*)d_in[3];
  const float* Wb   = (const float*)d_in[4];
  const float* Wtg  = (const float*)d_in[5];
  const float* ml   = (const float*)d_in[6];
  const float* ldc  = (const float*)d_in[7];
  const float* oms  = (const float*)d_in[8];
  const float* Wg   = (const float*)d_in[9];
  const float* Wo   = (const float*)d_in[10];
  float* out = (float*)d_out;

  proj_gemm_kernel<<<dim3(NPROJ / 64, NROWS / 64), 256>>>(x, Wq, Wk, Wv, Wb, Wtg, Wg);
  zero_y_kernel<<<(NROWS * HH * DV + 255) / 256, 256>>>();
  scan_kernel<<<BB * HH * RRm, 256>>>(ml, ldc, oms);
  out_gemm_kernel<<<dim3(DD / 64, NROWS / 64), 256>>>(Wo, out);
}

// round 2
// speedup vs baseline: 1.3074x; 1.3074x over previous
#include <cuda_runtime.h>
#include <math.h>

// Problem constants
#define BB 2
#define TT 128
#define DD 1024
#define HH 8
#define RRm 8
#define DK 64
#define DV 64
#define NPROJ 2176           // 512 q | 512 k | 512 v | 64 beta | 64 tg | 512 g
#define NROWS 256            // B*T

typedef unsigned long long u64;

// Scratch (no allocations allowed)
__device__ __align__(16) float g_proj[NROWS * NPROJ];          // 2.2 MB
__device__ __align__(16) float g_yr[RRm * NROWS * 512];        // 4 MB  (per-r mode reads)
__device__ __align__(16) float g_a[NROWS * 512];               // 512 KB (gated, r-reduced)

// ---------------------------------------------------------------------------
// f32x2 helpers (ptxas never emits FFMA2 from C++; PTX only)
// ---------------------------------------------------------------------------
__device__ __forceinline__ u64 pack2(float lo, float hi) {
  u64 r; asm("mov.b64 %0, {%1, %2};" : "=l"(r) : "f"(lo), "f"(hi)); return r;
}
__device__ __forceinline__ void unpack2(u64 v, float& lo, float& hi) {
  asm("mov.b64 {%0, %1}, %2;" : "=f"(lo), "=f"(hi) : "l"(v));
}
__device__ __forceinline__ u64 fma2(u64 a, u64 b, u64 c) {
  u64 d; asm("fma.rn.f32x2 %0, %1, %2, %3;" : "=l"(d) : "l"(a), "l"(b), "l"(c)); return d;
}
__device__ __forceinline__ u64 mul2(u64 a, u64 b) {
  u64 d; asm("mul.rn.f32x2 %0, %1, %2;" : "=l"(d) : "l"(a), "l"(b)); return d;
}
__device__ __forceinline__ u64 neg2(u64 a) { return a ^ 0x8000000080000000ULL; }

union F4U { float4 f; u64 u[2]; };

__device__ __forceinline__ float sigmoidf_(float x) { return 1.f / (1.f + expf(-x)); }

// ---------------------------------------------------------------------------
// Fused projection GEMM: proj[256, 2176] = x @ [Wq|Wk|Wv|Wb|Wtg|Wg]
// 64x64 tiles, 256 threads, 4x4 microtile via f32x2. Sigmoid for cols >= 1536.
// ---------------------------------------------------------------------------
__global__ __launch_bounds__(256) void proj_gemm_kernel(
    const float* __restrict__ x,
    const float* __restrict__ Wq, const float* __restrict__ Wk,
    const float* __restrict__ Wv, const float* __restrict__ Wb,
    const float* __restrict__ Wtg, const float* __restrict__ Wg) {
  __shared__ float As[16][64];
  __shared__ float Bs[16][64];

  const int colBase = blockIdx.x * 64;
  const int rowBase = blockIdx.y * 64;

  const float* W; int lc, ldw;
  if (colBase < 512)       { W = Wq;  lc = colBase;        ldw = 512; }
  else if (colBase < 1024) { W = Wk;  lc = colBase - 512;  ldw = 512; }
  else if (colBase < 1536) { W = Wv;  lc = colBase - 1024; ldw = 512; }
  else if (colBase < 1600) { W = Wb;  lc = colBase - 1536; ldw = 64;  }
  else if (colBase < 1664) { W = Wtg; lc = colBase - 1600; ldw = 64;  }
  else                     { W = Wg;  lc = colBase - 1664; ldw = 512; }

  const int tid = threadIdx.x;
  const int ty = tid >> 4, tx = tid & 15;        // compute mapping
  const int lr = tid >> 2, kg = tid & 3;         // A load mapping
  const int lk = tid >> 4, c4 = (tid & 15) << 2; // B load mapping

  u64 acc[4][2];
#pragma unroll
  for (int i = 0; i < 4; i++) { acc[i][0] = 0ULL; acc[i][1] = 0ULL; }

  for (int kb = 0; kb < DD; kb += 16) {
    float4 av = *(const float4*)(x + (rowBase + lr) * DD + kb + kg * 4);
    float4 bv = *(const float4*)(W + (kb + lk) * ldw + lc + c4);
    __syncthreads();
    As[kg * 4 + 0][lr] = av.x;
    As[kg * 4 + 1][lr] = av.y;
    As[kg * 4 + 2][lr] = av.z;
    As[kg * 4 + 3][lr] = av.w;
    *(float4*)(&Bs[lk][c4]) = bv;
    __syncthreads();
#pragma unroll
    for (int kk = 0; kk < 16; kk++) {
      float4 aa = *(float4*)(&As[kk][ty * 4]);
      F4U bb; bb.f = *(float4*)(&Bs[kk][tx * 4]);
      u64 a0 = pack2(aa.x, aa.x);
      u64 a1 = pack2(aa.y, aa.y);
      u64 a2 = pack2(aa.z, aa.z);
      u64 a3 = pack2(aa.w, aa.w);
      acc[0][0] = fma2(a0, bb.u[0], acc[0][0]);
      acc[0][1] = fma2(a0, bb.u[1], acc[0][1]);
      acc[1][0] = fma2(a1, bb.u[0], acc[1][0]);
      acc[1][1] = fma2(a1, bb.u[1], acc[1][1]);
      acc[2][0] = fma2(a2, bb.u[0], acc[2][0]);
      acc[2][1] = fma2(a2, bb.u[1], acc[2][1]);
      acc[3][0] = fma2(a3, bb.u[0], acc[3][0]);
      acc[3][1] = fma2(a3, bb.u[1], acc[3][1]);
    }
  }

  const bool sig = (colBase >= 1536);
#pragma unroll
  for (int i = 0; i < 4; i++) {
    F4U o; o.u[0] = acc[i][0]; o.u[1] = acc[i][1];
    if (sig) {
      o.f.x = sigmoidf_(o.f.x); o.f.y = sigmoidf_(o.f.y);
      o.f.z = sigmoidf_(o.f.z); o.f.w = sigmoidf_(o.f.w);
    }
    *(float4*)(g_proj + (rowBase + ty * 4 + i) * NPROJ + colBase + tx * 4) = o.f;
  }
}

// ---------------------------------------------------------------------------
// Sequential scan. One CTA per (b,h,r) chain: 128 CTAs, 256 threads.
// Thread owns v = tid/4 (row), k-slice [16*(tid%4), +16) as 8 f32x2 pairs.
// omega uses (k & ~1) so each f32x2 pair shares one cos/sin.
// ---------------------------------------------------------------------------
__global__ __launch_bounds__(256) void scan_kernel(
    const float* __restrict__ mode_logits,
    const float* __restrict__ log_decay,
    const float* __restrict__ omega_log_scale) {
  const int cid = blockIdx.x;        // 0..127
  const int b = cid >> 6;
  const int h = (cid >> 3) & 7;
  const int r = cid & 7;
  const int tid = threadIdx.x;
  const int v = tid >> 2;
  const int q4 = tid & 3;
  const int k0 = q4 * 16;

  // mode weight: softmax over R for this head
  float ml[RRm];
  float mx = -1e30f;
#pragma unroll
  for (int i = 0; i < RRm; i++) { ml[i] = mode_logits[h * RRm + i]; mx = fmaxf(mx, ml[i]); }
  float ssum = 0.f;
#pragma unroll
  for (int i = 0; i < RRm; i++) ssum += expf(ml[i] - mx);
  const float mw = expf(ml[r] - mx) / ssum;

  // rho = exp(-softplus(log_decay))
  const float ldv = log_decay[h * RRm + r];
  const float sp = (ldv > 20.f) ? ldv : log1pf(expf(ldv));
  const float rho = expf(-sp);
  const float osc = expf(omega_log_scale[h * RRm + r]);

  u64 cw2[8], sw2[8], sr2[8], si2[8];
  const float c_ln = 9.210340371976184f / 64.f;  // ln(10000)/64
#pragma unroll
  for (int p = 0; p < 8; p++) {
    float pv = (float)(k0 + 2 * p);              // even -> (k & ~1) identical for pair
    float om = osc * expf(-pv * c_ln);
    float c = cosf(om), s = sinf(om);
    cw2[p] = pack2(c, c);
    sw2[p] = pack2(s, s);
    sr2[p] = 0ULL;
    si2[p] = 0ULL;
  }

  const int qoff = h * DK + k0;
  float* ybase = g_yr + r * (NROWS * 512) + (b * TT) * 512 + h * DV + v;

  for (int t = 0; t < TT; t++) {
    const float* row = g_proj + (b * TT + t) * NPROJ;

    u64 kt2[8], qt2[8];
#pragma unroll
    for (int g4 = 0; g4 < 4; g4++) {
      F4U kv; kv.f = *(const float4*)(row + 512 + qoff + g4 * 4);
      F4U qv; qv.f = *(const float4*)(row + 0 + qoff + g4 * 4);
      kt2[g4 * 2 + 0] = kv.u[0]; kt2[g4 * 2 + 1] = kv.u[1];
      qt2[g4 * 2 + 0] = qv.u[0]; qt2[g4 * 2 + 1] = qv.u[1];
    }
    const float vtv  = row[1024 + h * DV + v];
    const float beta = row[1536 + h * RRm + r];  // pre-sigmoided
    const float tg   = row[1600 + h * RRm + r];  // pre-sigmoided
    const float decay = tg * rho;
    const u64 decay2 = pack2(decay, decay);

    // rotate state (complex mult by decay * e^{i omega}) + pred partial
    u64 pred2 = 0ULL;
#pragma unroll
    for (int p = 0; p < 8; p++) {
      u64 dc = mul2(decay2, cw2[p]);
      u64 ds = mul2(decay2, sw2[p]);
      u64 m1 = mul2(ds, si2[p]);
      u64 rr = fma2(dc, sr2[p], neg2(m1));
      u64 m2 = mul2(dc, si2[p]);
      si2[p] = fma2(ds, sr2[p], m2);
      sr2[p] = rr;                       // sr temporarily holds rot_r
      pred2 = fma2(rr, kt2[p], pred2);
    }
    float plo, phi; unpack2(pred2, plo, phi);
    float pred = plo + phi;
    pred += __shfl_xor_sync(0xffffffffu, pred, 1);
    pred += __shfl_xor_sync(0xffffffffu, pred, 2);

    const float w = beta * (vtv - pred);
    const u64 w2 = pack2(w, w);

    u64 rd2 = 0ULL;
#pragma unroll
    for (int p = 0; p < 8; p++) {
      sr2[p] = fma2(w2, kt2[p], sr2[p]); // sr_new = rot_r + beta*err*k
      rd2 = fma2(sr2[p], qt2[p], rd2);
    }
    float rlo, rhi; unpack2(rd2, rlo, rhi);
    float rd = rlo + rhi;
    rd += __shfl_xor_sync(0xffffffffu, rd, 1);
    rd += __shfl_xor_sync(0xffffffffu, rd, 2);

    if (q4 == 0) ybase[t * 512] = mw * rd;
  }
}

// ---------------------------------------------------------------------------
// Reduce over r + apply gate: g_a[row][c] = gate[row][c] * sum_r g_yr[r][row][c]
// ---------------------------------------------------------------------------
__global__ __launch_bounds__(256) void reduce_y_kernel() {
  int idx = blockIdx.x * blockDim.x + threadIdx.x;   // float4 index
  if (idx >= NROWS * 512 / 4) return;
  int row = idx >> 7;           // 128 float4 per row
  int c4 = (idx & 127) << 2;
  float4 s = *(const float4*)(g_yr + row * 512 + c4);
#pragma unroll
  for (int r = 1; r < RRm; r++) {
    float4 t = *(const float4*)(g_yr + r * (NROWS * 512) + row * 512 + c4);
    s.x += t.x; s.y += t.y; s.z += t.z; s.w += t.w;
  }
  float4 g = *(const float4*)(g_proj + row * NPROJ + 1664 + c4);
  s.x *= g.x; s.y *= g.y; s.z *= g.z; s.w *= g.w;
  *(float4*)(g_a + row * 512 + c4) = s;
}

// ---------------------------------------------------------------------------
// Output GEMM: out[256,1024] = g_a[256,512] @ Wo[512,1024]
// 32x64 tiles -> grid (16,8) = 128 CTAs. 256 threads, 2x4 microtile via f32x2.
// ---------------------------------------------------------------------------
__global__ __launch_bounds__(256) void out_gemm_kernel(
    const float* __restrict__ Wo, float* __restrict__ out) {
  __shared__ float As[16][32];
  __shared__ float Bs[16][64];

  const int colBase = blockIdx.x * 64;  // 0..1023
  const int rowBase = blockIdx.y * 32;  // 0..255

  const int tid = threadIdx.x;
  const int ry = (tid >> 4) * 2;        // row pair within tile
  const int cx = (tid & 15) * 4;        // 4 cols
  const int lk = tid >> 4, c4b = (tid & 15) << 2;

  u64 acc[2][2] = {{0ULL, 0ULL}, {0ULL, 0ULL}};

  for (int kb = 0; kb < 512; kb += 16) {
    float4 av;
    if (tid < 128) {
      int lr = tid >> 2, kg = tid & 3;
      av = *(const float4*)(g_a + (rowBase + lr) * 512 + kb + kg * 4);
    }
    float4 bv = *(const float4*)(Wo + (kb + lk) * DD + colBase + c4b);
    __syncthreads();
    if (tid < 128) {
      int lr = tid >> 2, kg = tid & 3;
      As[kg * 4 + 0][lr] = av.x;
      As[kg * 4 + 1][lr] = av.y;
      As[kg * 4 + 2][lr] = av.z;
      As[kg * 4 + 3][lr] = av.w;
    }
    *(float4*)(&Bs[lk][c4b]) = bv;
    __syncthreads();
#pragma unroll
    for (int kk = 0; kk < 16; kk++) {
      float2 a2 = *(float2*)(&As[kk][ry]);
      F4U bb; bb.f = *(float4*)(&Bs[kk][cx]);
      u64 a0 = pack2(a2.x, a2.x);
      u64 a1 = pack2(a2.y, a2.y);
      acc[0][0] = fma2(a0, bb.u[0], acc[0][0]);
      acc[0][1] = fma2(a0, bb.u[1], acc[0][1]);
      acc[1][0] = fma2(a1, bb.u[0], acc[1][0]);
      acc[1][1] = fma2(a1, bb.u[1], acc[1][1]);
    }
  }

#pragma unroll
  for (int i = 0; i < 2; i++) {
    F4U o; o.u[0] = acc[i][0]; o.u[1] = acc[i][1];
    *(float4*)(out + (rowBase + ry + i) * DD + colBase + cx) = o.f;
  }
}

// ---------------------------------------------------------------------------
// Entry point
// ---------------------------------------------------------------------------
extern "C" void kernel_launch(void* const* d_in, const int* in_sizes, int n_in,
                              void* d_out, int out_size) {
  const float* x    = (const float*)d_in[0];
  const float* Wq   = (const float*)d_in[1];
  const float* Wk   = (const float*)d_in[2];
  const float* Wv   = (const float*)d_in[3];
  const float* Wb   = (const float*)d_in[4];
  const float* Wtg  = (const float*)d_in[5];
  const float* ml   = (const float*)d_in[6];
  const float* ldc  = (const float*)d_in[7];
  const float* oms  = (const float*)d_in[8];
  const float* Wg   = (const float*)d_in[9];
  const float* Wo   = (const float*)d_in[10];
  float* out = (float*)d_out;

  proj_gemm_kernel<<<dim3(NPROJ / 64, NROWS / 64), 256>>>(x, Wq, Wk, Wv, Wb, Wtg, Wg);
  scan_kernel<<<BB * HH * RRm, 256>>>(ml, ldc, oms);
  reduce_y_kernel<<<(NROWS * 512 / 4 + 255) / 256, 256>>>();
  out_gemm_kernel<<<dim3(DD / 64, NROWS / 32), 256>>>(Wo, out);
}

// round 3
// speedup vs baseline: 2.0549x; 1.5717x over previous
#include <cuda_runtime.h>
#include <math.h>

// Problem constants
#define BB 2
#define TT 128
#define DD 1024
#define HH 8
#define RRm 8
#define DK 64
#define DV 64
#define NPROJ 2176           // 512 q | 512 k | 512 v | 64 beta | 64 tg | 512 g
#define NROWS 256            // B*T

typedef unsigned long long u64;

// Scratch (no allocations allowed)
__device__ __align__(16) float g_proj[NROWS * NPROJ];          // 2.2 MB
__device__ __align__(16) float g_yr[RRm * NROWS * 512];        // 4 MB  (per-r mode reads)
__device__ __align__(16) float g_a[NROWS * 512];               // 512 KB (gated, r-reduced)

// ---------------------------------------------------------------------------
// f32x2 helpers (ptxas never emits FFMA2 from C++; PTX only)
// ---------------------------------------------------------------------------
__device__ __forceinline__ u64 pack2(float lo, float hi) {
  u64 r; asm("mov.b64 %0, {%1, %2};" : "=l"(r) : "f"(lo), "f"(hi)); return r;
}
__device__ __forceinline__ void unpack2(u64 v, float& lo, float& hi) {
  asm("mov.b64 {%0, %1}, %2;" : "=f"(lo), "=f"(hi) : "l"(v));
}
__device__ __forceinline__ u64 fma2(u64 a, u64 b, u64 c) {
  u64 d; asm("fma.rn.f32x2 %0, %1, %2, %3;" : "=l"(d) : "l"(a), "l"(b), "l"(c)); return d;
}
__device__ __forceinline__ u64 mul2(u64 a, u64 b) {
  u64 d; asm("mul.rn.f32x2 %0, %1, %2;" : "=l"(d) : "l"(a), "l"(b)); return d;
}
__device__ __forceinline__ u64 neg2(u64 a) { return a ^ 0x8000000080000000ULL; }

union F4U { float4 f; u64 u[2]; };

__device__ __forceinline__ float sigmoidf_(float x) { return 1.f / (1.f + expf(-x)); }

// ---------------------------------------------------------------------------
// Fused projection GEMM: proj[256, 2176] = x @ [Wq|Wk|Wv|Wb|Wtg|Wg]
// 32x64 tiles -> grid (34, 8) = 272 CTAs (2/SM). Double-buffered smem,
// one __syncthreads per k-tile. 2x4 microtile via f32x2. Sigmoid >= col 1536.
// ---------------------------------------------------------------------------
__global__ __launch_bounds__(256) void proj_gemm_kernel(
    const float* __restrict__ x,
    const float* __restrict__ Wq, const float* __restrict__ Wk,
    const float* __restrict__ Wv, const float* __restrict__ Wb,
    const float* __restrict__ Wtg, const float* __restrict__ Wg) {
  __shared__ float As[2][16][32];
  __shared__ float Bs[2][16][64];

  const int colBase = blockIdx.x * 64;
  const int rowBase = blockIdx.y * 32;

  const float* W; int lc, ldw;
  if (colBase < 512)       { W = Wq;  lc = colBase;        ldw = 512; }
  else if (colBase < 1024) { W = Wk;  lc = colBase - 512;  ldw = 512; }
  else if (colBase < 1536) { W = Wv;  lc = colBase - 1024; ldw = 512; }
  else if (colBase < 1600) { W = Wb;  lc = colBase - 1536; ldw = 64;  }
  else if (colBase < 1664) { W = Wtg; lc = colBase - 1600; ldw = 64;  }
  else                     { W = Wg;  lc = colBase - 1664; ldw = 512; }

  const int tid = threadIdx.x;
  const int ty = tid >> 4, tx = tid & 15;        // compute: rows ty*2+, cols tx*4+
  const int lrA = tid >> 2, kgA = tid & 3;       // A load (threads 0..127)
  const int lkB = tid >> 4, c4B = (tid & 15) << 2;

  u64 acc[2][2] = {{0ULL, 0ULL}, {0ULL, 0ULL}};

  const int NIT = DD / 16;
  float4 av, bv;
  if (tid < 128) av = *(const float4*)(x + (rowBase + lrA) * DD + kgA * 4);
  bv = *(const float4*)(W + lkB * ldw + lc + c4B);
  if (tid < 128) {
    As[0][kgA * 4 + 0][lrA] = av.x;
    As[0][kgA * 4 + 1][lrA] = av.y;
    As[0][kgA * 4 + 2][lrA] = av.z;
    As[0][kgA * 4 + 3][lrA] = av.w;
  }
  *(float4*)(&Bs[0][lkB][c4B]) = bv;
  __syncthreads();

  int cur = 0;
  for (int i = 0; i < NIT; i++) {
    if (i + 1 < NIT) {
      int kb = (i + 1) * 16;
      if (tid < 128) av = *(const float4*)(x + (rowBase + lrA) * DD + kb + kgA * 4);
      bv = *(const float4*)(W + (kb + lkB) * ldw + lc + c4B);
    }
#pragma unroll
    for (int kk = 0; kk < 16; kk++) {
      float2 a2 = *(float2*)(&As[cur][kk][ty * 2]);
      F4U bb; bb.f = *(float4*)(&Bs[cur][kk][tx * 4]);
      u64 a0 = pack2(a2.x, a2.x);
      u64 a1 = pack2(a2.y, a2.y);
      acc[0][0] = fma2(a0, bb.u[0], acc[0][0]);
      acc[0][1] = fma2(a0, bb.u[1], acc[0][1]);
      acc[1][0] = fma2(a1, bb.u[0], acc[1][0]);
      acc[1][1] = fma2(a1, bb.u[1], acc[1][1]);
    }
    if (i + 1 < NIT) {
      int nxt = cur ^ 1;
      if (tid < 128) {
        As[nxt][kgA * 4 + 0][lrA] = av.x;
        As[nxt][kgA * 4 + 1][lrA] = av.y;
        As[nxt][kgA * 4 + 2][lrA] = av.z;
        As[nxt][kgA * 4 + 3][lrA] = av.w;
      }
      *(float4*)(&Bs[nxt][lkB][c4B]) = bv;
      __syncthreads();
      cur = nxt;
    }
  }

  const bool sig = (colBase >= 1536);
#pragma unroll
  for (int i = 0; i < 2; i++) {
    F4U o; o.u[0] = acc[i][0]; o.u[1] = acc[i][1];
    if (sig) {
      o.f.x = sigmoidf_(o.f.x); o.f.y = sigmoidf_(o.f.y);
      o.f.z = sigmoidf_(o.f.z); o.f.w = sigmoidf_(o.f.w);
    }
    *(float4*)(g_proj + (rowBase + ty * 2 + i) * NPROJ + colBase + tx * 4) = o.f;
  }
}

// ---------------------------------------------------------------------------
// Sequential scan. One CTA per (b,h,r) chain: 128 CTAs, 256 threads.
// Thread owns v = tid/4 (row), k-slice [16*(tid%4), +16) as 8 f32x2 pairs.
// Software pipeline: t+1's q/k/v/beta/tg prefetched into registers while
// computing step t -> L2 latency off the serial critical path.
// ---------------------------------------------------------------------------
__global__ __launch_bounds__(256) void scan_kernel(
    const float* __restrict__ mode_logits,
    const float* __restrict__ log_decay,
    const float* __restrict__ omega_log_scale) {
  const int cid = blockIdx.x;        // 0..127
  const int b = cid >> 6;
  const int h = (cid >> 3) & 7;
  const int r = cid & 7;
  const int tid = threadIdx.x;
  const int v = tid >> 2;
  const int q4 = tid & 3;
  const int k0 = q4 * 16;

  // mode weight: softmax over R for this head
  float ml[RRm];
  float mx = -1e30f;
#pragma unroll
  for (int i = 0; i < RRm; i++) { ml[i] = mode_logits[h * RRm + i]; mx = fmaxf(mx, ml[i]); }
  float ssum = 0.f;
#pragma unroll
  for (int i = 0; i < RRm; i++) ssum += expf(ml[i] - mx);
  const float mw = expf(ml[r] - mx) / ssum;

  // rho = exp(-softplus(log_decay))
  const float ldv = log_decay[h * RRm + r];
  const float sp = (ldv > 20.f) ? ldv : log1pf(expf(ldv));
  const float rho = expf(-sp);
  const float osc = expf(omega_log_scale[h * RRm + r]);

  u64 cw2[8], sw2[8], sr2[8], si2[8];
  const float c_ln = 9.210340371976184f / 64.f;  // ln(10000)/64
#pragma unroll
  for (int p = 0; p < 8; p++) {
    float pv = (float)(k0 + 2 * p);              // even -> (k & ~1) identical for pair
    float om = osc * expf(-pv * c_ln);
    float c = cosf(om), s = sinf(om);
    cw2[p] = pack2(c, c);
    sw2[p] = pack2(s, s);
    sr2[p] = 0ULL;
    si2[p] = 0ULL;
  }

  const int qoff = h * DK + k0;
  const float* rowBase = g_proj + (b * TT) * NPROJ;
  float* ybase = g_yr + r * (NROWS * 512) + (b * TT) * 512 + h * DV + v;

  // Prefetch t = 0
  F4U kbuf[4], qbuf[4];
  float vn, betan, tgn;
#pragma unroll
  for (int g4 = 0; g4 < 4; g4++) {
    kbuf[g4].f = *(const float4*)(rowBase + 512 + qoff + g4 * 4);
    qbuf[g4].f = *(const float4*)(rowBase + qoff + g4 * 4);
  }
  vn    = rowBase[1024 + h * DV + v];
  betan = rowBase[1536 + h * RRm + r];
  tgn   = rowBase[1600 + h * RRm + r];

  for (int t = 0; t < TT; t++) {
    u64 kt2[8], qt2[8];
#pragma unroll
    for (int g4 = 0; g4 < 4; g4++) {
      kt2[g4 * 2 + 0] = kbuf[g4].u[0]; kt2[g4 * 2 + 1] = kbuf[g4].u[1];
      qt2[g4 * 2 + 0] = qbuf[g4].u[0]; qt2[g4 * 2 + 1] = qbuf[g4].u[1];
    }
    const float vtv = vn, beta = betan, tg = tgn;

    // Prefetch t+1 (independent of state -> hides L2 latency)
    if (t + 1 < TT) {
      const float* row = rowBase + (t + 1) * NPROJ;
#pragma unroll
      for (int g4 = 0; g4 < 4; g4++) {
        kbuf[g4].f = *(const float4*)(row + 512 + qoff + g4 * 4);
        qbuf[g4].f = *(const float4*)(row + qoff + g4 * 4);
      }
      vn    = row[1024 + h * DV + v];
      betan = row[1536 + h * RRm + r];
      tgn   = row[1600 + h * RRm + r];
    }

    const float decay = tg * rho;
    const u64 decay2 = pack2(decay, decay);

    // rotate state (complex mult by decay * e^{i omega}) + pred partial
    u64 predA = 0ULL, predB = 0ULL;
#pragma unroll
    for (int p = 0; p < 8; p++) {
      u64 dc = mul2(decay2, cw2[p]);
      u64 ds = mul2(decay2, sw2[p]);
      u64 m1 = mul2(ds, si2[p]);
      u64 rr = fma2(dc, sr2[p], neg2(m1));
      u64 m2 = mul2(dc, si2[p]);
      si2[p] = fma2(ds, sr2[p], m2);
      sr2[p] = rr;                       // sr temporarily holds rot_r
      if (p & 1) predB = fma2(rr, kt2[p], predB);
      else       predA = fma2(rr, kt2[p], predA);
    }
    u64 pred2; {
      float alo, ahi, blo, bhi;
      unpack2(predA, alo, ahi); unpack2(predB, blo, bhi);
      pred2 = pack2(alo + blo, ahi + bhi);
    }
    float plo, phi; unpack2(pred2, plo, phi);
    float pred = plo + phi;
    pred += __shfl_xor_sync(0xffffffffu, pred, 1);
    pred += __shfl_xor_sync(0xffffffffu, pred, 2);

    const float w = beta * (vtv - pred);
    const u64 w2 = pack2(w, w);

    u64 rdA = 0ULL, rdB = 0ULL;
#pragma unroll
    for (int p = 0; p < 8; p++) {
      sr2[p] = fma2(w2, kt2[p], sr2[p]); // sr_new = rot_r + beta*err*k
      if (p & 1) rdB = fma2(sr2[p], qt2[p], rdB);
      else       rdA = fma2(sr2[p], qt2[p], rdA);
    }
    float r0lo, r0hi, r1lo, r1hi;
    unpack2(rdA, r0lo, r0hi); unpack2(rdB, r1lo, r1hi);
    float rd = (r0lo + r1lo) + (r0hi + r1hi);
    rd += __shfl_xor_sync(0xffffffffu, rd, 1);
    rd += __shfl_xor_sync(0xffffffffu, rd, 2);

    if (q4 == 0) ybase[t * 512] = mw * rd;
  }
}

// ---------------------------------------------------------------------------
// Reduce over r + apply gate: g_a[row][c] = gate[row][c] * sum_r g_yr[r][row][c]
// ---------------------------------------------------------------------------
__global__ __launch_bounds__(256) void reduce_y_kernel() {
  int idx = blockIdx.x * blockDim.x + threadIdx.x;   // float4 index
  if (idx >= NROWS * 512 / 4) return;
  int row = idx >> 7;           // 128 float4 per row
  int c4 = (idx & 127) << 2;
  float4 s = *(const float4*)(g_yr + row * 512 + c4);
#pragma unroll
  for (int r = 1; r < RRm; r++) {
    float4 t = *(const float4*)(g_yr + r * (NROWS * 512) + row * 512 + c4);
    s.x += t.x; s.y += t.y; s.z += t.z; s.w += t.w;
  }
  float4 g = *(const float4*)(g_proj + row * NPROJ + 1664 + c4);
  s.x *= g.x; s.y *= g.y; s.z *= g.z; s.w *= g.w;
  *(float4*)(g_a + row * 512 + c4) = s;
}

// ---------------------------------------------------------------------------
// Output GEMM: out[256,1024] = g_a[256,512] @ Wo[512,1024]
// 32x64 tiles -> grid (16,8) = 128 CTAs. Double-buffered smem, one sync/tile.
// ---------------------------------------------------------------------------
__global__ __launch_bounds__(256) void out_gemm_kernel(
    const float* __restrict__ Wo, float* __restrict__ out) {
  __shared__ float As[2][16][32];
  __shared__ float Bs[2][16][64];

  const int colBase = blockIdx.x * 64;  // 0..1023
  const int rowBase = blockIdx.y * 32;  // 0..255

  const int tid = threadIdx.x;
  const int ty = tid >> 4, tx = tid & 15;
  const int lrA = tid >> 2, kgA = tid & 3;
  const int lkB = tid >> 4, c4B = (tid & 15) << 2;

  u64 acc[2][2] = {{0ULL, 0ULL}, {0ULL, 0ULL}};

  const int NIT = 512 / 16;
  float4 av, bv;
  if (tid < 128) av = *(const float4*)(g_a + (rowBase + lrA) * 512 + kgA * 4);
  bv = *(const float4*)(Wo + lkB * DD + colBase + c4B);
  if (tid < 128) {
    As[0][kgA * 4 + 0][lrA] = av.x;
    As[0][kgA * 4 + 1][lrA] = av.y;
    As[0][kgA * 4 + 2][lrA] = av.z;
    As[0][kgA * 4 + 3][lrA] = av.w;
  }
  *(float4*)(&Bs[0][lkB][c4B]) = bv;
  __syncthreads();

  int cur = 0;
  for (int i = 0; i < NIT; i++) {
    if (i + 1 < NIT) {
      int kb = (i + 1) * 16;
      if (tid < 128) av = *(const float4*)(g_a + (rowBase + lrA) * 512 + kb + kgA * 4);
      bv = *(const float4*)(Wo + (kb + lkB) * DD + colBase + c4B);
    }
#pragma unroll
    for (int kk = 0; kk < 16; kk++) {
      float2 a2 = *(float2*)(&As[cur][kk][ty * 2]);
      F4U bb; bb.f = *(float4*)(&Bs[cur][kk][tx * 4]);
      u64 a0 = pack2(a2.x, a2.x);
      u64 a1 = pack2(a2.y, a2.y);
      acc[0][0] = fma2(a0, bb.u[0], acc[0][0]);
      acc[0][1] = fma2(a0, bb.u[1], acc[0][1]);
      acc[1][0] = fma2(a1, bb.u[0], acc[1][0]);
      acc[1][1] = fma2(a1, bb.u[1], acc[1][1]);
    }
    if (i + 1 < NIT) {
      int nxt = cur ^ 1;
      if (tid < 128) {
        As[nxt][kgA * 4 + 0][lrA] = av.x;
        As[nxt][kgA * 4 + 1][lrA] = av.y;
        As[nxt][kgA * 4 + 2][lrA] = av.z;
        As[nxt][kgA * 4 + 3][lrA] = av.w;
      }
      *(float4*)(&Bs[nxt][lkB][c4B]) = bv;
      __syncthreads();
      cur = nxt;
    }
  }

#pragma unroll
  for (int i = 0; i < 2; i++) {
    F4U o; o.u[0] = acc[i][0]; o.u[1] = acc[i][1];
    *(float4*)(out + (rowBase + ty * 2 + i) * DD + colBase + tx * 4) = o.f;
  }
}

// ---------------------------------------------------------------------------
// Entry point
// ---------------------------------------------------------------------------
extern "C" void kernel_launch(void* const* d_in, const int* in_sizes, int n_in,
                              void* d_out, int out_size) {
  const float* x    = (const float*)d_in[0];
  const float* Wq   = (const float*)d_in[1];
  const float* Wk   = (const float*)d_in[2];
  const float* Wv   = (const float*)d_in[3];
  const float* Wb   = (const float*)d_in[4];
  const float* Wtg  = (const float*)d_in[5];
  const float* ml   = (const float*)d_in[6];
  const float* ldc  = (const float*)d_in[7];
  const float* oms  = (const float*)d_in[8];
  const float* Wg   = (const float*)d_in[9];
  const float* Wo   = (const float*)d_in[10];
  float* out = (float*)d_out;

  proj_gemm_kernel<<<dim3(NPROJ / 64, NROWS / 32), 256>>>(x, Wq, Wk, Wv, Wb, Wtg, Wg);
  scan_kernel<<<BB * HH * RRm, 256>>>(ml, ldc, oms);
  reduce_y_kernel<<<(NROWS * 512 / 4 + 255) / 256, 256>>>();
  out_gemm_kernel<<<dim3(DD / 64, NROWS / 32), 256>>>(Wo, out);
}